// round 14
// baseline (speedup 1.0000x reference)
#include <cuda_runtime.h>
#include <cuda_fp16.h>
#include <math.h>
#include <stdint.h>

#define SB 32
#define SH 2048
#define ST 39
#define SV 8000
#define SE 50

__device__ __forceinline__ float sigf(float x){ return 1.0f/(1.0f + expf(-x)); }

__device__ __forceinline__ uint32_t s2u(const void* p){
    uint32_t a; asm("{ .reg .u64 t; cvta.to.shared.u64 t, %1; cvt.u32.u64 %0, t; }" : "=r"(a) : "l"(p)); return a;
}
__device__ __forceinline__ void minit(uint32_t m, uint32_t c){
    asm volatile("mbarrier.init.shared.b64 [%0], %1;" :: "r"(m), "r"(c) : "memory");
}
__device__ __forceinline__ void mexpect(uint32_t m, uint32_t tx){
    asm volatile("mbarrier.arrive.expect_tx.shared.b64 _, [%0], %1;" :: "r"(m), "r"(tx) : "memory");
}
__device__ __forceinline__ void mwait(uint32_t m, uint32_t ph){
    asm volatile("{ .reg .pred P; L%=: mbarrier.try_wait.parity.acquire.cta.shared::cta.b64 P, [%0], %1; @P bra D%=; bra L%=; D%=: }"
                 :: "r"(m), "r"(ph) : "memory");
}
__device__ __forceinline__ void bulkcp(uint32_t dst, const void* src, uint32_t bytes, uint32_t mbar){
    asm volatile("cp.async.bulk.shared::cluster.global.mbarrier::complete_tx::bytes [%0], [%1], %2, [%3];"
                 :: "r"(dst), "l"(src), "r"(bytes), "r"(mbar) : "memory");
}
__device__ __forceinline__ void ldm4(uint32_t* r, uint32_t a){
    asm volatile("ldmatrix.sync.aligned.m8n8.x4.shared.b16 {%0,%1,%2,%3}, [%4];"
        : "=r"(r[0]),"=r"(r[1]),"=r"(r[2]),"=r"(r[3]) : "r"(a));
}
__device__ __forceinline__ void hmma(float* c, const uint32_t* a, const uint32_t* b){
    asm volatile("mma.sync.aligned.m16n8k16.row.col.f32.f16.f16.f32 "
        "{%0,%1,%2,%3}, {%4,%5,%6,%7}, {%8,%9}, {%0,%1,%2,%3};"
        : "+f"(c[0]),"+f"(c[1]),"+f"(c[2]),"+f"(c[3])
        : "r"(a[0]),"r"(a[1]),"r"(a[2]),"r"(a[3]), "r"(b[0]),"r"(b[1]));
}

// ---------------- packed fp16 weights ----------------
__device__ __align__(128) __half g_LP[(size_t)64*32*128*64];   // LSTM Whh, gate-permuted (128-row blocks)
__device__ __align__(128) __half g_HP[(size_t)64*32*96*64];    // GRU Whh, gate-permuted (96-row blocks)
__device__ __align__(128) __half g_IP[(size_t)64*32*96*64];    // GRU Wih, gate-permuted (96-row blocks)
__device__ __align__(128) __half g_FP[(size_t)63*32*128*64];   // linW (rows >=8000 clamped)
// packed fp16 states: [ck64(32)][n(32)][64k swizzled]
__device__ __align__(128) __half d_hsP [2][32*32*64];
__device__ __align__(128) __half d_hgsP[2][32*32*64];
__device__ __align__(128) __half d_csP39[(size_t)ST*32*32*64];   // c for every step
__device__ __align__(128) __half d_FBP[(size_t)10*32*128*64];    // final B, groups of 4 timesteps
__device__ __align__(16) float d_Xg[(size_t)ST*4*SB*SH];     // [t][gate][b][k]
__device__ __align__(16) float d_cf[SB*SH];                  // [b][k]
__device__ __align__(16) float d_hgf[2][SB*SH];              // [b][k]
// sync state
__device__ int d_Lcnt, d_Lgen, d_Gcnt, d_Ggen;

// ---------------- prep ----------------
__global__ void reset_kernel(){
    if (threadIdx.x == 0){ d_Lcnt = 0; d_Lgen = 0; d_Gcnt = 0; d_Ggen = 0; }
}

// mode 0: identity rows (MR=128); 1: LSTM 128-row gate blocks; 2: GRU 96-row gate blocks
__global__ void packw_kernel(const float* __restrict__ src, __half* __restrict__ dst,
                             int mode, int MR){
    int i = blockIdx.x*256 + threadIdx.x;
    int r = i >> 8, u = i & 255;
    int k = u*8, ck = k >> 6, cc = (k >> 3) & 7;
    int p;
    if (mode == 0) p = r;
    else if (mode == 1){ int g = r>>11, j = r&2047; p = (j>>5)*128 + g*32 + (j&31); }
    else             { int g = r>>11, j = r&2047; p = (j>>5)*96  + g*32 + (j&31); }
    int mblk = p / MR, row = p % MR;
    size_t base = ((size_t)mblk*32 + ck)*((size_t)MR*64) + (size_t)row*64 + ((cc^(row&7))*8);
    const float4* s4 = (const float4*)(src + (size_t)r*SH + k);
    float4 v0 = s4[0], v1 = s4[1];
    float f[8] = {v0.x,v0.y,v0.z,v0.w,v1.x,v1.y,v1.z,v1.w};
    __half h[8];
    #pragma unroll
    for (int q = 0; q < 8; q++) h[q] = __float2half(f[q]);
    *(uint4*)(dst + base) = *(uint4*)h;
}

__device__ __forceinline__ int pkidx32(int b, int jg){
    int ck = jg >> 6, kk = jg & 63, cc = kk >> 3;
    return ck*2048 + b*64 + ((cc^(b&7))*8) + (kk&7);
}

__global__ void setup_kernel(const float* __restrict__ feat){
    int i = blockIdx.x*256 + threadIdx.x;   // 65536 = b*2048 + k
    int b = i >> 11, k = i & 2047;
    float v = feat[i];
    d_cf[b*SH + k] = v; d_hgf[0][b*SH + k] = v;
    __half h = __float2half(v);
    d_hsP[0][pkidx32(b,k)] = h;
    d_hgsP[0][pkidx32(b,k)] = h;
}

__global__ void xg_kernel(const int* __restrict__ captions, const float* __restrict__ emb,
                          const float* __restrict__ Wih, const float* __restrict__ bih,
                          const float* __restrict__ bhh){
    __shared__ float embS[SE*SB];
    __shared__ float tr[8][32*33];
    int t = blockIdx.x, jc = blockIdx.y, tid = threadIdx.x;
    int lane = tid & 31, wid = tid >> 5;
    for (int i = tid; i < SB*SE; i += 256){
        int b = i / SE, e = i % SE;
        int cap = captions[b*40 + t];
        embS[e*SB + b] = emb[(size_t)cap*SE + e];
    }
    __syncthreads();
    for (int rep = 0; rep < 4; rep++){
        int jbase = jc*1024 + rep*256 + wid*32;
        for (int jj = 0; jj < 32; jj++){
            int j = jbase + jj;
            float acc = bih[j] + bhh[j];
            const float* wr = Wih + (size_t)j*SE;
            #pragma unroll
            for (int e = 0; e < SE; e++) acc = fmaf(wr[e], embS[e*SB + lane], acc);
            tr[wid][jj*33 + lane] = acc;
        }
        __syncwarp();
        int g = jbase >> 11, col0 = jbase & 2047;
        for (int r = 0; r < 32; r++)
            d_Xg[((size_t)(t*4 + g)*SB + r)*SH + col0 + lane] = tr[wid][lane*33 + r];
        __syncwarp();
    }
}

// ---------------- global barrier (symmetric: all blocks of the grid) ----------------
__device__ __forceinline__ void gbar(int* cnt, int* gen, int nblk, int target, int tid){
    asm volatile("fence.proxy.async;" ::: "memory");
    __threadfence();
    __syncthreads();
    if (tid == 0){
        int a = atomicAdd(cnt, 1);
        if (a == nblk - 1){ atomicExch(cnt, 0); __threadfence(); atomicAdd(gen, 1); }
        while (atomicAdd(gen, 0) < target) __nanosleep(64);
        __threadfence();
    }
    __syncthreads();
}

// ---------------- bulk-pipelined fp16 GEMM core (NB=32, KC=128, 3 stages) ----------------
// requires blockDim.x == MR/16 * 32
template<int MR>
__device__ __forceinline__ void gemm_bulk(const __half* __restrict__ Apk,
                                          const __half* __restrict__ Bpk,
                                          char* sm, float (*c)[4]){
    const int ASZ = 2*MR*128, BSZ = 2*32*128, SS = ASZ + BSZ;
    uint32_t smb = s2u(sm);
    uint32_t mb = smb + 3*SS;
    int tid = threadIdx.x, l = tid & 31, w = tid >> 5;
    if (tid == 0){
        #pragma unroll
        for (int s = 0; s < 3; s++) minit(mb + 8*s, 1);
    }
    __syncthreads();
    auto issue = [&](int s, int ck){
        if (tid == 0){
            mexpect(mb + 8*s, (uint32_t)(ASZ + BSZ));
            bulkcp(smb + s*SS,       Apk + (size_t)ck*(2*MR*64), ASZ, mb + 8*s);
            bulkcp(smb + s*SS + ASZ, Bpk + (size_t)ck*(2*32*64), BSZ, mb + 8*s);
        }
    };
    issue(0,0); issue(1,1); issue(2,2);
    int rowA = w*16 + (l & 15);
    int nB0 = (l&7) + ((l&16)>>1);
    int cAdd = l >> 4, cBadd = (l>>3)&1;
    for (int ck = 0; ck < 16; ck++){
        int s = ck % 3;
        mwait(mb + 8*s, (ck/3)&1);
        uint32_t ab = smb + s*SS, bb = ab + ASZ;
        #pragma unroll
        for (int ks = 0; ks < 8; ks++){
            int gA = ks >> 2, cu = (ks & 3)*2;
            uint32_t a4[4];
            uint32_t aaddr = ab + gA*MR*128 + rowA*128 + (((cu + cAdd) ^ (rowA&7))<<4);
            ldm4(a4, aaddr);
            #pragma unroll
            for (int g = 0; g < 2; g++){
                uint32_t b4[4];
                int n = g*16 + nB0;
                uint32_t baddr = bb + gA*32*128 + n*128 + (((cu + cBadd) ^ (n&7))<<4);
                ldm4(b4, baddr);
                hmma(c[2*g],   a4, b4);
                hmma(c[2*g+1], a4, b4+2);
            }
        }
        __syncthreads();
        if (ck + 3 < 16) issue(s, ck + 3);
    }
}

#define SMEM_L  ((2*128*128 + 2*32*128)*3 + 64)
#define SMEM_G  ((2*96*128 + 2*32*128)*3 + 64)
#define SMEM_FIN ((2*128*128 + 2*128*128)*3 + 64)

// ---------------- persistent LSTM chain: 64 blocks x 256 threads ----------------
__global__ void __launch_bounds__(256, 1) persistL_kernel(){
    extern __shared__ char sm[];
    int tid = threadIdx.x, l = tid & 31, w = tid >> 5;
    int t4 = l >> 2, cb = (l & 3)*2;
    int vb = blockIdx.x;
    const __half* Apk = g_LP + (size_t)vb*(32*128*64);
    for (int t = 0; t < ST; t++){
        int rp = t & 1, wp = rp ^ 1;
        float c[4][4];
        #pragma unroll
        for (int i = 0; i < 4; i++){ c[i][0]=0.f; c[i][1]=0.f; c[i][2]=0.f; c[i][3]=0.f; }
        gemm_bulk<128>(Apk, d_hsP[rp], sm, c);
        __syncthreads();
        float* ex = (float*)sm;
        #pragma unroll
        for (int nt = 0; nt < 4; nt++){
            #pragma unroll
            for (int p = 0; p < 2; p++){
                int r = w*16 + t4 + p*8, col = nt*8 + cb;
                ex[r*33 + col]     = c[nt][2*p];
                ex[r*33 + col + 1] = c[nt][2*p+1];
            }
        }
        __syncthreads();
        #pragma unroll
        for (int it = 0; it < 4; it++){
            int id = it*256 + tid;
            int b = id >> 5, jl = id & 31;
            int jg = vb*32 + jl;
            float gi = ex[(     jl)*33 + b] + d_Xg[((size_t)(t*4+0)*SB + b)*SH + jg];
            float gf = ex[(32 + jl)*33 + b] + d_Xg[((size_t)(t*4+1)*SB + b)*SH + jg];
            float gg = ex[(64 + jl)*33 + b] + d_Xg[((size_t)(t*4+2)*SB + b)*SH + jg];
            float go = ex[(96 + jl)*33 + b] + d_Xg[((size_t)(t*4+3)*SB + b)*SH + jg];
            float cold = d_cf[b*SH + jg];
            float cn = sigf(gf)*cold + sigf(gi)*tanhf(gg);
            float hn = sigf(go)*tanhf(cn);
            d_cf[b*SH + jg] = cn;
            d_csP39[(size_t)t*2048*32 + pkidx32(b,jg)] = __float2half(cn);
            d_hsP[wp][pkidx32(b,jg)] = __float2half(hn);
        }
        gbar(&d_Lcnt, &d_Lgen, 64, t + 1, tid);
    }
}

// ---------------- persistent GRU chain: 64 blocks x 192 threads (96 permuted rows each) ----------------
__global__ void __launch_bounds__(192, 1) persistG_kernel(const float* __restrict__ gbih,
                                                          const float* __restrict__ gbhh){
    extern __shared__ char sm[];
    int tid = threadIdx.x, l = tid & 31, w = tid >> 5;
    int t4 = l >> 2, cb = (l & 3)*2;
    int vb = blockIdx.x;
    const __half* Ah = g_HP + (size_t)vb*(32*96*64);
    const __half* Ai = g_IP + (size_t)vb*(32*96*64);
    for (int t = 0; t < ST; t++){
        int rp = t & 1, wp = rp ^ 1;
        float cH[4][4], cI[4][4];
        #pragma unroll
        for (int i = 0; i < 4; i++){
            cH[i][0]=0.f; cH[i][1]=0.f; cH[i][2]=0.f; cH[i][3]=0.f;
            cI[i][0]=0.f; cI[i][1]=0.f; cI[i][2]=0.f; cI[i][3]=0.f;
        }
        gemm_bulk<96>(Ah, d_hgsP[rp], sm, cH);
        __syncthreads();
        gemm_bulk<96>(Ai, d_csP39 + (size_t)t*2048*32, sm, cI);
        __syncthreads();
        float* exH = (float*)sm;               // 96*33 floats
        float* exI = exH + 96*33;
        #pragma unroll
        for (int nt = 0; nt < 4; nt++){
            #pragma unroll
            for (int p = 0; p < 2; p++){
                int r = w*16 + t4 + p*8, col = nt*8 + cb;
                exH[r*33 + col]     = cH[nt][2*p];
                exH[r*33 + col + 1] = cH[nt][2*p+1];
                exI[r*33 + col]     = cI[nt][2*p];
                exI[r*33 + col + 1] = cI[nt][2*p+1];
            }
        }
        __syncthreads();
        int tg = t >> 2, tl = t & 3;
        for (int id = tid; id < 1024; id += 192){
            int b = id >> 5, jl = id & 31;
            int jg = vb*32 + jl;
            float gi0 = exI[(     jl)*33 + b] + gbih[jg];
            float gi1 = exI[(32 + jl)*33 + b] + gbih[SH + jg];
            float gi2 = exI[(64 + jl)*33 + b] + gbih[2*SH + jg];
            float gh0 = exH[(     jl)*33 + b] + gbhh[jg];
            float gh1 = exH[(32 + jl)*33 + b] + gbhh[SH + jg];
            float gh2 = exH[(64 + jl)*33 + b] + gbhh[2*SH + jg];
            float r_ = sigf(gi0 + gh0);
            float z_ = sigf(gi1 + gh1);
            float n_ = tanhf(gi2 + r_*gh2);
            float hgo = d_hgf[rp][b*SH + jg];
            float hg = (1.0f - z_)*n_ + z_*hgo;
            d_hgf[wp][b*SH + jg] = hg;
            __half hh = __float2half(hg);
            d_hgsP[wp][pkidx32(b,jg)] = hh;
            int n = tl*32 + b;
            int ck = jg >> 6, kk = jg & 63, cc = kk >> 3;
            size_t fb = (size_t)tg*(32*128*64) + (size_t)ck*(128*64) + n*64 + ((cc^(n&7))*8) + (kk&7);
            d_FBP[fb] = hh;
        }
        gbar(&d_Gcnt, &d_Ggen, 64, t + 1, tid);
    }
}

// ---------------- final projection: M=128, N=128 (4 timesteps), 63x10 ----------------
__device__ __forceinline__ void gemm_bulkF(const __half* __restrict__ Apk,
                                           const __half* __restrict__ Bpk,
                                           char* sm, float (*c)[4]){
    const int ASZ = 2*128*128, BSZ = 2*128*128, SS = ASZ + BSZ;
    uint32_t smb = s2u(sm);
    uint32_t mb = smb + 3*SS;
    int tid = threadIdx.x, l = tid & 31, w = tid >> 5;
    if (tid == 0){
        #pragma unroll
        for (int s = 0; s < 3; s++) minit(mb + 8*s, 1);
    }
    __syncthreads();
    auto issue = [&](int s, int ck){
        if (tid == 0){
            mexpect(mb + 8*s, (uint32_t)(ASZ + BSZ));
            bulkcp(smb + s*SS,       Apk + (size_t)ck*(2*128*64), ASZ, mb + 8*s);
            bulkcp(smb + s*SS + ASZ, Bpk + (size_t)ck*(2*128*64), BSZ, mb + 8*s);
        }
    };
    issue(0,0); issue(1,1); issue(2,2);
    int rowA = w*16 + (l & 15);
    int nB0 = (l&7) + ((l&16)>>1);
    int cAdd = l >> 4, cBadd = (l>>3)&1;
    for (int ck = 0; ck < 16; ck++){
        int s = ck % 3;
        mwait(mb + 8*s, (ck/3)&1);
        uint32_t ab = smb + s*SS, bb = ab + ASZ;
        #pragma unroll
        for (int ks = 0; ks < 8; ks++){
            int gA = ks >> 2, cu = (ks & 3)*2;
            uint32_t a4[4];
            uint32_t aaddr = ab + gA*128*128 + rowA*128 + (((cu + cAdd) ^ (rowA&7))<<4);
            ldm4(a4, aaddr);
            #pragma unroll
            for (int g = 0; g < 8; g++){
                uint32_t b4[4];
                int n = g*16 + nB0;
                uint32_t baddr = bb + gA*128*128 + n*128 + (((cu + cBadd) ^ (n&7))<<4);
                ldm4(b4, baddr);
                hmma(c[2*g],   a4, b4);
                hmma(c[2*g+1], a4, b4+2);
            }
        }
        __syncthreads();
        if (ck + 3 < 16) issue(s, ck + 3);
    }
}

__global__ void __launch_bounds__(256) mmaF_kernel(const float* __restrict__ linb,
                                                   float* __restrict__ out){
    extern __shared__ char sm[];
    int tid = threadIdx.x, l = tid & 31, w = tid >> 5;
    int m0 = blockIdx.x*128;
    int tg = blockIdx.y, t0 = tg*4;
    float c[16][4];
    #pragma unroll
    for (int i = 0; i < 16; i++){ c[i][0]=0.f; c[i][1]=0.f; c[i][2]=0.f; c[i][3]=0.f; }
    gemm_bulkF(g_FP + (size_t)blockIdx.x*(32*128*64),
               d_FBP + (size_t)tg*(32*128*64), sm, c);
    int validT = (tg == 9) ? 3 : 4;
    int t4 = l >> 2, cb = (l & 3)*2;
    #pragma unroll
    for (int nt = 0; nt < 16; nt++){
        int col = nt*8 + cb;
        int tl = col >> 5, b = col & 31;
        if (tl >= validT) continue;
        int tt = t0 + tl;
        #pragma unroll
        for (int p = 0; p < 2; p++){
            int v = m0 + w*16 + t4 + p*8;
            if (v < SV){
                float bias = linb[v];
                size_t o = (size_t)b*((size_t)ST*SV) + (size_t)tt*SV + v;
                out[o] = c[nt][2*p] + bias;
                out[o + (size_t)ST*SV] = c[nt][2*p+1] + bias;
            }
        }
    }
}

// ---------------- launch ----------------
extern "C" void kernel_launch(void* const* d_in, const int* in_sizes, int n_in,
                              void* d_out, int out_size){
    const float* features = (const float*)d_in[0];
    const int*   captions = (const int*)  d_in[1];
    const float* emb      = (const float*)d_in[2];
    const float* lWih     = (const float*)d_in[3];
    const float* lbih     = (const float*)d_in[4];
    const float* lWhh     = (const float*)d_in[5];
    const float* lbhh     = (const float*)d_in[6];
    const float* gWih     = (const float*)d_in[7];
    const float* gbih     = (const float*)d_in[8];
    const float* gWhh     = (const float*)d_in[9];
    const float* gbhh     = (const float*)d_in[10];
    const float* linW     = (const float*)d_in[11];
    const float* linb     = (const float*)d_in[12];
    float* out = (float*)d_out;

    cudaFuncSetAttribute(persistL_kernel, cudaFuncAttributeMaxDynamicSharedMemorySize, SMEM_L);
    cudaFuncSetAttribute(persistG_kernel, cudaFuncAttributeMaxDynamicSharedMemorySize, SMEM_G);
    cudaFuncSetAttribute(mmaF_kernel, cudaFuncAttributeMaxDynamicSharedMemorySize, SMEM_FIN);

    __half *pL, *pH, *pI, *pF;
    cudaGetSymbolAddress((void**)&pL, g_LP);
    cudaGetSymbolAddress((void**)&pH, g_HP);
    cudaGetSymbolAddress((void**)&pI, g_IP);
    cudaGetSymbolAddress((void**)&pF, g_FP);

    setup_kernel<<<256, 256>>>(features);
    packw_kernel<<<8192, 256>>>(lWhh, pL, 1, 128);
    packw_kernel<<<6144, 256>>>(gWhh, pH, 2, 96);
    packw_kernel<<<6144, 256>>>(gWih, pI, 2, 96);
    packw_kernel<<<8000, 256>>>(linW, pF, 0, 128);
    xg_kernel<<<dim3(ST, 8), 256>>>(captions, emb, lWih, lbih, lbhh);
    reset_kernel<<<1, 32>>>();
    persistL_kernel<<<64, 256, SMEM_L>>>();
    persistG_kernel<<<64, 192, SMEM_G>>>(gbih, gbhh);
    mmaF_kernel<<<dim3(63, 10), 256, SMEM_FIN>>>(linb, out);
}

// round 15
// speedup vs baseline: 1.6419x; 1.6419x over previous
#include <cuda_runtime.h>
#include <cuda_fp16.h>
#include <math.h>
#include <stdint.h>

#define SB 32
#define SH 2048
#define ST 39
#define SV 8000
#define SE 50

__device__ __forceinline__ float sigf(float x){ return 1.0f/(1.0f + expf(-x)); }

__device__ __forceinline__ uint32_t s2u(const void* p){
    uint32_t a; asm("{ .reg .u64 t; cvta.to.shared.u64 t, %1; cvt.u32.u64 %0, t; }" : "=r"(a) : "l"(p)); return a;
}
__device__ __forceinline__ void minit(uint32_t m, uint32_t c){
    asm volatile("mbarrier.init.shared.b64 [%0], %1;" :: "r"(m), "r"(c) : "memory");
}
__device__ __forceinline__ void mexpect(uint32_t m, uint32_t tx){
    asm volatile("mbarrier.arrive.expect_tx.shared.b64 _, [%0], %1;" :: "r"(m), "r"(tx) : "memory");
}
__device__ __forceinline__ void mwait(uint32_t m, uint32_t ph){
    asm volatile("{ .reg .pred P; L%=: mbarrier.try_wait.parity.acquire.cta.shared::cta.b64 P, [%0], %1; @P bra D%=; bra L%=; D%=: }"
                 :: "r"(m), "r"(ph) : "memory");
}
__device__ __forceinline__ void bulkcp(uint32_t dst, const void* src, uint32_t bytes, uint32_t mbar){
    asm volatile("cp.async.bulk.shared::cluster.global.mbarrier::complete_tx::bytes [%0], [%1], %2, [%3];"
                 :: "r"(dst), "l"(src), "r"(bytes), "r"(mbar) : "memory");
}
__device__ __forceinline__ void ldm4(uint32_t* r, uint32_t a){
    asm volatile("ldmatrix.sync.aligned.m8n8.x4.shared.b16 {%0,%1,%2,%3}, [%4];"
        : "=r"(r[0]),"=r"(r[1]),"=r"(r[2]),"=r"(r[3]) : "r"(a));
}
__device__ __forceinline__ void hmma(float* c, const uint32_t* a, const uint32_t* b){
    asm volatile("mma.sync.aligned.m16n8k16.row.col.f32.f16.f16.f32 "
        "{%0,%1,%2,%3}, {%4,%5,%6,%7}, {%8,%9}, {%0,%1,%2,%3};"
        : "+f"(c[0]),"+f"(c[1]),"+f"(c[2]),"+f"(c[3])
        : "r"(a[0]),"r"(a[1]),"r"(a[2]),"r"(a[3]), "r"(b[0]),"r"(b[1]));
}

// ---------------- packed fp16 weights ----------------
__device__ __align__(128) __half g_LP[(size_t)64*32*128*64];   // LSTM Whh, gate-permuted (128-row blocks)
__device__ __align__(128) __half g_HP[(size_t)64*32*96*64];    // GRU Whh, gate-permuted (96-row blocks)
__device__ __align__(128) __half g_IP[(size_t)64*32*96*64];    // GRU Wih, gate-permuted (96-row blocks)
__device__ __align__(128) __half g_FP[(size_t)63*32*128*64];   // linW (rows >=8000 clamped)
// packed fp16 states: [ck64(32)][n(32)][64k swizzled]
__device__ __align__(128) __half d_hsP [2][32*32*64];
__device__ __align__(128) __half d_hgsP[2][32*32*64];
__device__ __align__(128) __half d_csP39[(size_t)ST*32*32*64];   // c for every step
__device__ __align__(128) __half d_FBP[(size_t)10*32*128*64];    // final B, groups of 4 timesteps
__device__ __align__(16) float d_Xg[(size_t)ST*4*SB*SH];     // [t][gate][b][k]
__device__ __align__(16) float d_cf[SB*SH];                  // [b][k]
__device__ __align__(16) float d_hgf[2][SB*SH];              // [b][k]

// ---------------- prep ----------------
// mode 0: identity rows (MR=128); 1: LSTM 128-row gate blocks; 2: GRU 96-row gate blocks
__global__ void packw_kernel(const float* __restrict__ src, __half* __restrict__ dst,
                             int mode, int MR){
    int i = blockIdx.x*256 + threadIdx.x;
    int r = i >> 8, u = i & 255;
    int k = u*8, ck = k >> 6, cc = (k >> 3) & 7;
    int p;
    if (mode == 0) p = r;
    else if (mode == 1){ int g = r>>11, j = r&2047; p = (j>>5)*128 + g*32 + (j&31); }
    else             { int g = r>>11, j = r&2047; p = (j>>5)*96  + g*32 + (j&31); }
    int mblk = p / MR, row = p % MR;
    size_t base = ((size_t)mblk*32 + ck)*((size_t)MR*64) + (size_t)row*64 + ((cc^(row&7))*8);
    const float4* s4 = (const float4*)(src + (size_t)r*SH + k);
    float4 v0 = s4[0], v1 = s4[1];
    float f[8] = {v0.x,v0.y,v0.z,v0.w,v1.x,v1.y,v1.z,v1.w};
    __half h[8];
    #pragma unroll
    for (int q = 0; q < 8; q++) h[q] = __float2half(f[q]);
    *(uint4*)(dst + base) = *(uint4*)h;
}

__device__ __forceinline__ int pkidx32(int b, int jg){
    int ck = jg >> 6, kk = jg & 63, cc = kk >> 3;
    return ck*2048 + b*64 + ((cc^(b&7))*8) + (kk&7);
}

__global__ void setup_kernel(const float* __restrict__ feat){
    int i = blockIdx.x*256 + threadIdx.x;   // 65536 = b*2048 + k
    int b = i >> 11, k = i & 2047;
    float v = feat[i];
    d_cf[b*SH + k] = v; d_hgf[0][b*SH + k] = v;
    __half h = __float2half(v);
    d_hsP[0][pkidx32(b,k)] = h;
    d_hgsP[0][pkidx32(b,k)] = h;
}

__global__ void xg_kernel(const int* __restrict__ captions, const float* __restrict__ emb,
                          const float* __restrict__ Wih, const float* __restrict__ bih,
                          const float* __restrict__ bhh){
    __shared__ float embS[SE*SB];
    __shared__ float tr[8][32*33];
    int t = blockIdx.x, jc = blockIdx.y, tid = threadIdx.x;
    int lane = tid & 31, wid = tid >> 5;
    for (int i = tid; i < SB*SE; i += 256){
        int b = i / SE, e = i % SE;
        int cap = captions[b*40 + t];
        embS[e*SB + b] = emb[(size_t)cap*SE + e];
    }
    __syncthreads();
    for (int rep = 0; rep < 4; rep++){
        int jbase = jc*1024 + rep*256 + wid*32;
        for (int jj = 0; jj < 32; jj++){
            int j = jbase + jj;
            float acc = bih[j] + bhh[j];
            const float* wr = Wih + (size_t)j*SE;
            #pragma unroll
            for (int e = 0; e < SE; e++) acc = fmaf(wr[e], embS[e*SB + lane], acc);
            tr[wid][jj*33 + lane] = acc;
        }
        __syncwarp();
        int g = jbase >> 11, col0 = jbase & 2047;
        for (int r = 0; r < 32; r++)
            d_Xg[((size_t)(t*4 + g)*SB + r)*SH + col0 + lane] = tr[wid][lane*33 + r];
        __syncwarp();
    }
}

// ---------------- bulk-pipelined fp16 GEMM core (NB=32, KC=128, 3 stages) ----------------
// requires blockDim.x >= MR/16 * 32; extra warps only hit the syncthreads
template<int MR>
__device__ __forceinline__ void gemm_bulk(const __half* __restrict__ Apk,
                                          const __half* __restrict__ Bpk,
                                          char* sm, float (*c)[4]){
    const int ASZ = 2*MR*128, BSZ = 2*32*128, SS = ASZ + BSZ;
    uint32_t smb = s2u(sm);
    uint32_t mb = smb + 3*SS;
    int tid = threadIdx.x, l = tid & 31, w = tid >> 5;
    if (tid == 0){
        #pragma unroll
        for (int s = 0; s < 3; s++) minit(mb + 8*s, 1);
    }
    __syncthreads();
    auto issue = [&](int s, int ck){
        if (tid == 0){
            mexpect(mb + 8*s, (uint32_t)(ASZ + BSZ));
            bulkcp(smb + s*SS,       Apk + (size_t)ck*(2*MR*64), ASZ, mb + 8*s);
            bulkcp(smb + s*SS + ASZ, Bpk + (size_t)ck*(2*32*64), BSZ, mb + 8*s);
        }
    };
    issue(0,0); issue(1,1); issue(2,2);
    int rowA = w*16 + (l & 15);
    int nB0 = (l&7) + ((l&16)>>1);
    int cAdd = l >> 4, cBadd = (l>>3)&1;
    for (int ck = 0; ck < 16; ck++){
        int s = ck % 3;
        mwait(mb + 8*s, (ck/3)&1);
        uint32_t ab = smb + s*SS, bb = ab + ASZ;
        #pragma unroll
        for (int ks = 0; ks < 8; ks++){
            int gA = ks >> 2, cu = (ks & 3)*2;
            uint32_t a4[4];
            uint32_t aaddr = ab + gA*MR*128 + rowA*128 + (((cu + cAdd) ^ (rowA&7))<<4);
            ldm4(a4, aaddr);
            #pragma unroll
            for (int g = 0; g < 2; g++){
                uint32_t b4[4];
                int n = g*16 + nB0;
                uint32_t baddr = bb + gA*32*128 + n*128 + (((cu + cBadd) ^ (n&7))<<4);
                ldm4(b4, baddr);
                hmma(c[2*g],   a4, b4);
                hmma(c[2*g+1], a4, b4+2);
            }
        }
        __syncthreads();
        if (ck + 3 < 16) issue(s, ck + 3);
    }
}

#define SMEM_S  (3*65536 + 64)                      // dual-G layout bound (L uses less)
#define SMEM_FIN ((2*128*128 + 2*128*128)*3 + 64)

// ---------------- software-pipelined step kernel S(t), 128 blocks x 256 ----------------
// blocks 0..63  : LSTM step t      (t in 0..38)
// blocks 64..127: GRU  step t-1    (t-1 in 0..38)
__global__ void __launch_bounds__(256, 1) stepS_kernel(const float* __restrict__ gbih,
                                                       const float* __restrict__ gbhh, int t){
    extern __shared__ char sm[];
    int tid = threadIdx.x, l = tid & 31, w = tid >> 5;
    int t4 = l >> 2, cb = (l & 3)*2;
    if (blockIdx.x < 64){
        if (t >= ST) return;
        int vb = blockIdx.x;
        int rp = t & 1, wp = rp ^ 1;
        const __half* Apk = g_LP + (size_t)vb*(32*128*64);
        float c[4][4];
        #pragma unroll
        for (int i = 0; i < 4; i++){ c[i][0]=0.f; c[i][1]=0.f; c[i][2]=0.f; c[i][3]=0.f; }
        gemm_bulk<128>(Apk, d_hsP[rp], sm, c);
        __syncthreads();
        float* ex = (float*)sm;
        #pragma unroll
        for (int nt = 0; nt < 4; nt++){
            #pragma unroll
            for (int p = 0; p < 2; p++){
                int r = w*16 + t4 + p*8, col = nt*8 + cb;
                ex[r*33 + col]     = c[nt][2*p];
                ex[r*33 + col + 1] = c[nt][2*p+1];
            }
        }
        __syncthreads();
        #pragma unroll
        for (int it = 0; it < 4; it++){
            int id = it*256 + tid;
            int b = id >> 5, jl = id & 31;
            int jg = vb*32 + jl;
            float gi = ex[(     jl)*33 + b] + d_Xg[((size_t)(t*4+0)*SB + b)*SH + jg];
            float gf = ex[(32 + jl)*33 + b] + d_Xg[((size_t)(t*4+1)*SB + b)*SH + jg];
            float gg = ex[(64 + jl)*33 + b] + d_Xg[((size_t)(t*4+2)*SB + b)*SH + jg];
            float go = ex[(96 + jl)*33 + b] + d_Xg[((size_t)(t*4+3)*SB + b)*SH + jg];
            float cold = d_cf[b*SH + jg];
            float cn = sigf(gf)*cold + sigf(gi)*tanhf(gg);
            float hn = sigf(go)*tanhf(cn);
            d_cf[b*SH + jg] = cn;
            d_csP39[(size_t)t*2048*32 + pkidx32(b,jg)] = __float2half(cn);
            d_hsP[wp][pkidx32(b,jg)] = __float2half(hn);
        }
    } else {
        int tm = t - 1;
        if (tm < 0) return;
        int vb = blockIdx.x - 64;
        int rp = tm & 1, wp = rp ^ 1;
        const __half* Ah = g_HP + (size_t)vb*(32*96*64);
        const __half* Ai = g_IP + (size_t)vb*(32*96*64);
        const __half* Bh = d_hgsP[rp];
        const __half* Bi = d_csP39 + (size_t)tm*2048*32;
        // ---- fused dual-pipeline GEMM: MR=96 each, 6 active warps ----
        const int AS = 2*96*128, BS = 2*32*128, SS = 2*AS + 2*BS;   // 65536
        uint32_t smb = s2u(sm);
        uint32_t mb = smb + 3*SS;
        if (tid == 0){
            #pragma unroll
            for (int s = 0; s < 3; s++) minit(mb + 8*s, 1);
        }
        __syncthreads();
        auto issue = [&](int s, int ck){
            if (tid == 0){
                mexpect(mb + 8*s, (uint32_t)SS);
                bulkcp(smb + s*SS,             Ah + (size_t)ck*(2*96*64), AS, mb + 8*s);
                bulkcp(smb + s*SS + AS,        Ai + (size_t)ck*(2*96*64), AS, mb + 8*s);
                bulkcp(smb + s*SS + 2*AS,      Bh + (size_t)ck*(2*32*64), BS, mb + 8*s);
                bulkcp(smb + s*SS + 2*AS + BS, Bi + (size_t)ck*(2*32*64), BS, mb + 8*s);
            }
        };
        issue(0,0); issue(1,1); issue(2,2);
        float cH[4][4], cI[4][4];
        #pragma unroll
        for (int i = 0; i < 4; i++){
            cH[i][0]=0.f; cH[i][1]=0.f; cH[i][2]=0.f; cH[i][3]=0.f;
            cI[i][0]=0.f; cI[i][1]=0.f; cI[i][2]=0.f; cI[i][3]=0.f;
        }
        int rowA = w*16 + (l & 15);
        int nB0 = (l&7) + ((l&16)>>1);
        int cAdd = l >> 4, cBadd = (l>>3)&1;
        for (int ck = 0; ck < 16; ck++){
            int s = ck % 3;
            if (w < 6){
                mwait(mb + 8*s, (ck/3)&1);
                uint32_t ab = smb + s*SS, aib = ab + AS, bhb = ab + 2*AS, bib = bhb + BS;
                #pragma unroll
                for (int ks = 0; ks < 8; ks++){
                    int gA = ks >> 2, cu = (ks & 3)*2;
                    uint32_t a4h[4], a4i[4];
                    uint32_t aoff = gA*96*128 + rowA*128 + (((cu + cAdd) ^ (rowA&7))<<4);
                    ldm4(a4h, ab + aoff);
                    ldm4(a4i, aib + aoff);
                    #pragma unroll
                    for (int g = 0; g < 2; g++){
                        uint32_t b4[4];
                        int n = g*16 + nB0;
                        uint32_t boff = gA*32*128 + n*128 + (((cu + cBadd) ^ (n&7))<<4);
                        ldm4(b4, bhb + boff);
                        hmma(cH[2*g],   a4h, b4);
                        hmma(cH[2*g+1], a4h, b4+2);
                        ldm4(b4, bib + boff);
                        hmma(cI[2*g],   a4i, b4);
                        hmma(cI[2*g+1], a4i, b4+2);
                    }
                }
            }
            __syncthreads();
            if (ck + 3 < 16) issue(s, ck + 3);
        }
        __syncthreads();
        float* exH = (float*)sm;               // 96*33 floats
        float* exI = exH + 96*33;
        if (w < 6){
            #pragma unroll
            for (int nt = 0; nt < 4; nt++){
                #pragma unroll
                for (int p = 0; p < 2; p++){
                    int r = w*16 + t4 + p*8, col = nt*8 + cb;
                    exH[r*33 + col]     = cH[nt][2*p];
                    exH[r*33 + col + 1] = cH[nt][2*p+1];
                    exI[r*33 + col]     = cI[nt][2*p];
                    exI[r*33 + col + 1] = cI[nt][2*p+1];
                }
            }
        }
        __syncthreads();
        int tg = tm >> 2, tl = tm & 3;
        #pragma unroll
        for (int it = 0; it < 4; it++){
            int id = it*256 + tid;
            int b = id >> 5, jl = id & 31;
            int jg = vb*32 + jl;
            float gi0 = exI[(     jl)*33 + b] + gbih[jg];
            float gi1 = exI[(32 + jl)*33 + b] + gbih[SH + jg];
            float gi2 = exI[(64 + jl)*33 + b] + gbih[2*SH + jg];
            float gh0 = exH[(     jl)*33 + b] + gbhh[jg];
            float gh1 = exH[(32 + jl)*33 + b] + gbhh[SH + jg];
            float gh2 = exH[(64 + jl)*33 + b] + gbhh[2*SH + jg];
            float r_ = sigf(gi0 + gh0);
            float z_ = sigf(gi1 + gh1);
            float n_ = tanhf(gi2 + r_*gh2);
            float hgo = d_hgf[rp][b*SH + jg];
            float hg = (1.0f - z_)*n_ + z_*hgo;
            d_hgf[wp][b*SH + jg] = hg;
            __half hh = __float2half(hg);
            d_hgsP[wp][pkidx32(b,jg)] = hh;
            int n = tl*32 + b;
            int ck = jg >> 6, kk = jg & 63, cc = kk >> 3;
            size_t fb = (size_t)tg*(32*128*64) + (size_t)ck*(128*64) + n*64 + ((cc^(n&7))*8) + (kk&7);
            d_FBP[fb] = hh;
        }
    }
}

// ---------------- final projection: M=128, N=128 (4 timesteps), 63x10 ----------------
__device__ __forceinline__ void gemm_bulkF(const __half* __restrict__ Apk,
                                           const __half* __restrict__ Bpk,
                                           char* sm, float (*c)[4]){
    const int ASZ = 2*128*128, BSZ = 2*128*128, SS = ASZ + BSZ;
    uint32_t smb = s2u(sm);
    uint32_t mb = smb + 3*SS;
    int tid = threadIdx.x, l = tid & 31, w = tid >> 5;
    if (tid == 0){
        #pragma unroll
        for (int s = 0; s < 3; s++) minit(mb + 8*s, 1);
    }
    __syncthreads();
    auto issue = [&](int s, int ck){
        if (tid == 0){
            mexpect(mb + 8*s, (uint32_t)(ASZ + BSZ));
            bulkcp(smb + s*SS,       Apk + (size_t)ck*(2*128*64), ASZ, mb + 8*s);
            bulkcp(smb + s*SS + ASZ, Bpk + (size_t)ck*(2*128*64), BSZ, mb + 8*s);
        }
    };
    issue(0,0); issue(1,1); issue(2,2);
    int rowA = w*16 + (l & 15);
    int nB0 = (l&7) + ((l&16)>>1);
    int cAdd = l >> 4, cBadd = (l>>3)&1;
    for (int ck = 0; ck < 16; ck++){
        int s = ck % 3;
        mwait(mb + 8*s, (ck/3)&1);
        uint32_t ab = smb + s*SS, bb = ab + ASZ;
        #pragma unroll
        for (int ks = 0; ks < 8; ks++){
            int gA = ks >> 2, cu = (ks & 3)*2;
            uint32_t a4[4];
            uint32_t aaddr = ab + gA*128*128 + rowA*128 + (((cu + cAdd) ^ (rowA&7))<<4);
            ldm4(a4, aaddr);
            #pragma unroll
            for (int g = 0; g < 8; g++){
                uint32_t b4[4];
                int n = g*16 + nB0;
                uint32_t baddr = bb + gA*128*128 + n*128 + (((cu + cBadd) ^ (n&7))<<4);
                ldm4(b4, baddr);
                hmma(c[2*g],   a4, b4);
                hmma(c[2*g+1], a4, b4+2);
            }
        }
        __syncthreads();
        if (ck + 3 < 16) issue(s, ck + 3);
    }
}

__global__ void __launch_bounds__(256) mmaF_kernel(const float* __restrict__ linb,
                                                   float* __restrict__ out){
    extern __shared__ char sm[];
    int tid = threadIdx.x, l = tid & 31, w = tid >> 5;
    int m0 = blockIdx.x*128;
    int tg = blockIdx.y, t0 = tg*4;
    float c[16][4];
    #pragma unroll
    for (int i = 0; i < 16; i++){ c[i][0]=0.f; c[i][1]=0.f; c[i][2]=0.f; c[i][3]=0.f; }
    gemm_bulkF(g_FP + (size_t)blockIdx.x*(32*128*64),
               d_FBP + (size_t)tg*(32*128*64), sm, c);
    int validT = (tg == 9) ? 3 : 4;
    int t4 = l >> 2, cb = (l & 3)*2;
    #pragma unroll
    for (int nt = 0; nt < 16; nt++){
        int col = nt*8 + cb;
        int tl = col >> 5, b = col & 31;
        if (tl >= validT) continue;
        int tt = t0 + tl;
        #pragma unroll
        for (int p = 0; p < 2; p++){
            int v = m0 + w*16 + t4 + p*8;
            if (v < SV){
                float bias = linb[v];
                size_t o = (size_t)b*((size_t)ST*SV) + (size_t)tt*SV + v;
                out[o] = c[nt][2*p] + bias;
                out[o + (size_t)ST*SV] = c[nt][2*p+1] + bias;
            }
        }
    }
}

// ---------------- launch ----------------
extern "C" void kernel_launch(void* const* d_in, const int* in_sizes, int n_in,
                              void* d_out, int out_size){
    const float* features = (const float*)d_in[0];
    const int*   captions = (const int*)  d_in[1];
    const float* emb      = (const float*)d_in[2];
    const float* lWih     = (const float*)d_in[3];
    const float* lbih     = (const float*)d_in[4];
    const float* lWhh     = (const float*)d_in[5];
    const float* lbhh     = (const float*)d_in[6];
    const float* gWih     = (const float*)d_in[7];
    const float* gbih     = (const float*)d_in[8];
    const float* gWhh     = (const float*)d_in[9];
    const float* gbhh     = (const float*)d_in[10];
    const float* linW     = (const float*)d_in[11];
    const float* linb     = (const float*)d_in[12];
    float* out = (float*)d_out;

    cudaFuncSetAttribute(stepS_kernel, cudaFuncAttributeMaxDynamicSharedMemorySize, SMEM_S);
    cudaFuncSetAttribute(mmaF_kernel, cudaFuncAttributeMaxDynamicSharedMemorySize, SMEM_FIN);

    __half *pL, *pH, *pI, *pF;
    cudaGetSymbolAddress((void**)&pL, g_LP);
    cudaGetSymbolAddress((void**)&pH, g_HP);
    cudaGetSymbolAddress((void**)&pI, g_IP);
    cudaGetSymbolAddress((void**)&pF, g_FP);

    setup_kernel<<<256, 256>>>(features);
    packw_kernel<<<8192, 256>>>(lWhh, pL, 1, 128);
    packw_kernel<<<6144, 256>>>(gWhh, pH, 2, 96);
    packw_kernel<<<6144, 256>>>(gWih, pI, 2, 96);
    packw_kernel<<<8000, 256>>>(linW, pF, 0, 128);
    xg_kernel<<<dim3(ST, 8), 256>>>(captions, emb, lWih, lbih, lbhh);

    for (int t = 0; t <= ST; t++)
        stepS_kernel<<<128, 256, SMEM_S>>>(gbih, gbhh, t);
    mmaF_kernel<<<dim3(63, 10), 256, SMEM_FIN>>>(linb, out);
}